// round 6
// baseline (speedup 1.0000x reference)
#include <cuda_runtime.h>
#include <math.h>

#define HIDDEN     2048
#define SEQ        4096
#define BATCH      8
#define NCHUNK     64
#define CHUNK      (SEQ / NCHUNK)      // 64 rows per chunk
#define NBLK       (BATCH * NCHUNK)    // 512 blocks in kernel 1
#define TOTAL_RANK 16
#define ACTIVE_RANK 8
#define ADAPT_DIM  32
#define LN_EPS     1e-5f

// Scratch (no allocations allowed in kernel_launch)
__device__ float g_partial[NBLK * HIDDEN];                 // 4 MB, L2-resident
__device__ float g_M[BATCH * TOTAL_RANK * TOTAL_RANK];
__device__ unsigned int g_ticket;                          // zero-initialized

// ---------------------------------------------------------------------------
// Kernel 1 (fused): each of 512 blocks sums a 64-row S-chunk of
// hidden_states (the 256 MB read, coalesced float4 + __ldcs streaming).
// The LAST block to finish (atomic ticket) then performs the entire
// controller: pooled mean -> @W1 -> LN -> GELU -> @W2 -> top-8 -> bake M.
// Output is deterministic: the tail reads all partials after the fence,
// and the math is independent of which block runs it.
// ---------------------------------------------------------------------------
__global__ __launch_bounds__(512) void k_main(
    const float* __restrict__ hs,
    const float* __restrict__ W1, const float* __restrict__ b1,
    const float* __restrict__ gamma, const float* __restrict__ beta,
    const float* __restrict__ W2, const float* __restrict__ b2,
    const float* __restrict__ ml, const float* __restrict__ rs)
{
    const unsigned FULL = 0xFFFFFFFFu;
    int blk = blockIdx.x;
    int b   = blk >> 6;          // / NCHUNK
    int c   = blk & (NCHUNK - 1);
    int t   = threadIdx.x;
    int w   = t >> 5;
    int l   = t & 31;

    // --- phase 1: partial sum of this block's 64x2048 slab ---
    {
        const float4* p = reinterpret_cast<const float4*>(
            hs + ((size_t)(b * SEQ + c * CHUNK)) * HIDDEN) + t;
        float4 a0 = make_float4(0.f, 0.f, 0.f, 0.f);
        float4 a1 = make_float4(0.f, 0.f, 0.f, 0.f);
#pragma unroll 16
        for (int i = 0; i < CHUNK; i += 2) {
            float4 v0 = __ldcs(p + (size_t)(i)     * (HIDDEN / 4));
            float4 v1 = __ldcs(p + (size_t)(i + 1) * (HIDDEN / 4));
            a0.x += v0.x; a0.y += v0.y; a0.z += v0.z; a0.w += v0.w;
            a1.x += v1.x; a1.y += v1.y; a1.z += v1.z; a1.w += v1.w;
        }
        a0.x += a1.x; a0.y += a1.y; a0.z += a1.z; a0.w += a1.w;
        reinterpret_cast<float4*>(g_partial + (size_t)blk * HIDDEN)[t] = a0;
    }

    // --- ticket: last block through does the controller tail ---
    __threadfence();
    __shared__ unsigned int sIsLast;
    __syncthreads();                 // all stores issued before the vote
    if (t == 0)
        sIsLast = (atomicAdd(&g_ticket, 1u) == NBLK - 1u);
    __syncthreads();
    if (!sIsLast) return;

    // ======== tail: runs in exactly one block, 512 threads ========
    __shared__ float sPooled[HIDDEN];            // 8 KB
    __shared__ float sAcc[16][ADAPT_DIM];        // 2 KB
    __shared__ float sX[ADAPT_DIM];

    // Loop over all 8 batches serially (tiny work: ~1.2 MFLOP total).
    for (int bb = 0; bb < BATCH; bb++) {
        // (A) pooled mean: thread t owns columns 4t..4t+3
        {
            const float4* p = reinterpret_cast<const float4*>(
                g_partial + (size_t)bb * NCHUNK * HIDDEN) + t;
            float4 s0 = make_float4(0.f, 0.f, 0.f, 0.f);
            float4 s1 = make_float4(0.f, 0.f, 0.f, 0.f);
#pragma unroll 8
            for (int cc = 0; cc < NCHUNK; cc += 2) {
                float4 v0 = p[(size_t)(cc)     * (HIDDEN / 4)];
                float4 v1 = p[(size_t)(cc + 1) * (HIDDEN / 4)];
                s0.x += v0.x; s0.y += v0.y; s0.z += v0.z; s0.w += v0.w;
                s1.x += v1.x; s1.y += v1.y; s1.z += v1.z; s1.w += v1.w;
            }
            s0.x += s1.x; s0.y += s1.y; s0.z += s1.z; s0.w += s1.w;
            const float inv = 1.0f / SEQ;
            sPooled[4 * t + 0] = s0.x * inv;
            sPooled[4 * t + 1] = s0.y * inv;
            sPooled[4 * t + 2] = s0.z * inv;
            sPooled[4 * t + 3] = s0.w * inv;
        }
        __syncthreads();

        // (B) x = pooled @ W1 : warp w covers h in [w*128, w*128+128)
        {
            float acc = 0.f;
            int h0 = w * 128;
#pragma unroll 4
            for (int i = 0; i < 128; i++) {
                int h = h0 + i;
                acc += sPooled[h] * W1[h * ADAPT_DIM + l];
            }
            sAcc[w][l] = acc;
        }
        __syncthreads();

        // (C) controller: warp 0 only
        if (w == 0) {
            float x = 0.f;
#pragma unroll
            for (int j = 0; j < 16; j++) x += sAcc[j][l];
            x += b1[l];

            // LayerNorm over 32 lanes (population variance)
            float mu = x;
#pragma unroll
            for (int o = 16; o; o >>= 1) mu += __shfl_xor_sync(FULL, mu, o);
            mu *= (1.0f / ADAPT_DIM);
            float d = x - mu;
            float v = d * d;
#pragma unroll
            for (int o = 16; o; o >>= 1) v += __shfl_xor_sync(FULL, v, o);
            v *= (1.0f / ADAPT_DIM);
            x = d * rsqrtf(v + LN_EPS) * gamma[l] + beta[l];

            // exact GELU
            x = 0.5f * x * (1.0f + erff(x * 0.70710678118654752f));
            sX[l] = x;
            __syncwarp();

            // logits[r] = sum_a x[a] * W2[a,r] via shuffle broadcast
            float acc = 0.f;
#pragma unroll
            for (int a = 0; a < ADAPT_DIM; a++) {
                float xa = __shfl_sync(FULL, sX[l], 0); // placeholder, replaced below
                (void)xa;
                break;
            }
            acc = 0.f;
#pragma unroll
            for (int a = 0; a < ADAPT_DIM; a++) {
                float xa = sX[a];
                if (l < TOTAL_RANK) acc += xa * W2[a * TOTAL_RANK + l];
            }
            float comb = (l < TOTAL_RANK) ? (acc + b2[l] + ml[l]) : -1e30f;

            // top-8 of 16, lax.top_k tie semantics (lower index wins)
            int cnt = 0;
#pragma unroll
            for (int j = 0; j < TOTAL_RANK; j++) {
                float cj = __shfl_sync(FULL, comb, j);
                if (l < TOTAL_RANK && (cj > comb || (cj == comb && j < l))) cnt++;
            }
            float factor = (l < TOTAL_RANK && cnt < ACTIVE_RANK) ? rs[l] : 0.f;

            // M[b][d][r] = factor[r] * (-1)^popc(d&r) / 32
            if (l < TOTAL_RANK) {
#pragma unroll
                for (int dd = 0; dd < TOTAL_RANK; dd++) {
                    float sgn = (__popc(dd & l) & 1) ? -1.0f : 1.0f;
                    g_M[(bb * TOTAL_RANK + dd) * TOTAL_RANK + l] =
                        factor * sgn * (1.0f / 32.0f);
                }
            }
        }
        __syncthreads();
    }

    // reset ticket for next graph replay
    if (t == 0) g_ticket = 0u;
}

// ---------------------------------------------------------------------------
// Kernel 2: out[b,s,d] = sum_r rank_act[b,s,r] * M[b][d][r]
// One token per thread; 16 blocks per batch -> M broadcast from shared.
// ---------------------------------------------------------------------------
__global__ __launch_bounds__(256) void k_out(const float* __restrict__ ra,
                                             float* __restrict__ out) {
    __shared__ float sM[TOTAL_RANK * TOTAL_RANK];
    int tid = threadIdx.x;
    int t   = blockIdx.x * 256 + tid;       // token id, 32768 total
    int b   = blockIdx.x >> 4;              // 16 blocks per batch

    if (tid < TOTAL_RANK * TOTAL_RANK)
        sM[tid] = g_M[b * TOTAL_RANK * TOTAL_RANK + tid];
    __syncthreads();

    const float4* ap = reinterpret_cast<const float4*>(ra) + (size_t)t * 4;
    float4 a0 = ap[0], a1 = ap[1], a2 = ap[2], a3 = ap[3];
    float av[16] = {a0.x, a0.y, a0.z, a0.w, a1.x, a1.y, a1.z, a1.w,
                    a2.x, a2.y, a2.z, a2.w, a3.x, a3.y, a3.z, a3.w};

    float o[16];
#pragma unroll
    for (int dd = 0; dd < 16; dd++) {
        float s = 0.f;
#pragma unroll
        for (int r = 0; r < 16; r++) s += av[r] * sM[dd * 16 + r];
        o[dd] = s;
    }
    float4* op = reinterpret_cast<float4*>(out) + (size_t)t * 4;
    op[0] = make_float4(o[0],  o[1],  o[2],  o[3]);
    op[1] = make_float4(o[4],  o[5],  o[6],  o[7]);
    op[2] = make_float4(o[8],  o[9],  o[10], o[11]);
    op[3] = make_float4(o[12], o[13], o[14], o[15]);
}

// ---------------------------------------------------------------------------
extern "C" void kernel_launch(void* const* d_in, const int* in_sizes, int n_in,
                              void* d_out, int out_size) {
    const float* hs    = (const float*)d_in[0];
    const float* ra    = (const float*)d_in[1];
    const float* W1    = (const float*)d_in[2];
    const float* b1    = (const float*)d_in[3];
    const float* gamma = (const float*)d_in[4];
    const float* beta  = (const float*)d_in[5];
    const float* W2    = (const float*)d_in[6];
    const float* b2    = (const float*)d_in[7];
    const float* ml    = (const float*)d_in[8];
    const float* rs    = (const float*)d_in[9];
    float* out = (float*)d_out;

    k_main<<<NBLK, 512>>>(hs, W1, b1, gamma, beta, W2, b2, ml, rs);
    k_out<<<128, 256>>>(ra, out);
}